// round 11
// baseline (speedup 1.0000x reference)
#include <cuda_runtime.h>
#include <cuda_fp16.h>
#include <math.h>
#include <stdint.h>
#include <stddef.h>

// ---------------- problem constants ----------------
#define DIMC   384
#define NHEADS 12
#define HD     32
#define NTOK   64
#define NROWS  65536
#define HIDF   1536
#define QKVN   1152

// ---------------- scratch ----------------
__device__ float g_a[(size_t)NROWS * DIMC];   // ln outs (fp16 payload)
__device__ float g_b[(size_t)NROWS * HIDF];   // qkv fp16 / gelu out fp16
__device__ float g_c[(size_t)NROWS * DIMC];   // attention ctx (fp16 payload)
__device__ float g_d[(size_t)NROWS * DIMC];   // x + attn (token order, fp32)
// fp16 transposed weights [N][K]
__device__ __half g_w[442368 + 147456 + 589824 + 589824];

__device__ __forceinline__ int win_row_to_token(int r) {
    int b   = r >> 12;
    int rem = r & 4095;
    int wh  = rem >> 9;
    int ww  = (rem >> 6) & 7;
    int n   = rem & 63;
    int ys  = (wh * 8 + (n >> 3) + 4) & 63;
    int xs  = (ww * 8 + (n & 7) + 4) & 63;
    return (b << 12) + ys * 64 + xs;
}

// ---------------- weight prep: W[K][N] fp32 -> Wt[N][K] fp16 ----------------
__global__ __launch_bounds__(256) void transpose_f16_kernel(
    const float* __restrict__ src, __half* __restrict__ dst, int K, int N)
{
    __shared__ float tile[32][33];
    int bx = blockIdx.x * 32;
    int by = blockIdx.y * 32;
    int tx = threadIdx.x & 31;
    int ty = threadIdx.x >> 5;
    #pragma unroll
    for (int j = 0; j < 32; j += 8)
        tile[ty + j][tx] = src[(size_t)(by + ty + j) * N + bx + tx];
    __syncthreads();
    #pragma unroll
    for (int j = 0; j < 32; j += 8)
        dst[(size_t)(bx + ty + j) * K + by + tx] = __float2half_rn(tile[tx][ty + j]);
}

// ---------------- LayerNorm (fp16 output) ------------------------------------
__global__ __launch_bounds__(128) void ln_kernel(
    const float* __restrict__ x, const float* __restrict__ gam,
    const float* __restrict__ bet, __half* __restrict__ out, int gather)
{
    int r   = blockIdx.x;
    int src = gather ? win_row_to_token(r) : r;
    const float* xp = x + (size_t)src * DIMC;
    int t = threadIdx.x;

    float v0 = xp[t], v1 = xp[t + 128], v2 = xp[t + 256];
    float s  = v0 + v1 + v2;
    float ss = v0 * v0 + v1 * v1 + v2 * v2;
    #pragma unroll
    for (int o = 16; o; o >>= 1) {
        s  += __shfl_xor_sync(0xffffffffu, s,  o);
        ss += __shfl_xor_sync(0xffffffffu, ss, o);
    }
    __shared__ float sh[8];
    int w = t >> 5;
    if ((t & 31) == 0) { sh[w] = s; sh[4 + w] = ss; }
    __syncthreads();
    s  = sh[0] + sh[1] + sh[2] + sh[3];
    ss = sh[4] + sh[5] + sh[6] + sh[7];
    float mu  = s * (1.0f / DIMC);
    float var = ss * (1.0f / DIMC) - mu * mu;
    float inv = rsqrtf(var + 1e-5f);
    __half* op = out + (size_t)r * DIMC;
    op[t]       = __float2half_rn((v0 - mu) * inv * gam[t]       + bet[t]);
    op[t + 128] = __float2half_rn((v1 - mu) * inv * gam[t + 128] + bet[t + 128]);
    op[t + 256] = __float2half_rn((v2 - mu) * inv * gam[t + 256] + bet[t + 256]);
}

// ================= fp16 mma.sync GEMM, 256x128 tile, 512 threads =============
// A[M][K] fp16 row-major, Bt[N][K] fp16, both k-contiguous.
// 5-stage cp.async ring, one __syncthreads per iteration, LDSM fragments.
// mode bits: 1 = exact GELU, 2 = fp16 output, 4 = scatter rows + residual
#define BM 256
#define BN 128
#define HBK 32
#define A_BYTES (BM * 80)              // 20480
#define B_BYTES (BN * 80)              // 10240
#define STG     (A_BYTES + B_BYTES)    // 30720
#define NSTG    5

__device__ __forceinline__ void cp16(uint32_t smem, const void* g) {
    asm volatile("cp.async.cg.shared.global [%0], [%1], 16;\n"
                 :: "r"(smem), "l"(g));
}
#define CP_COMMIT() asm volatile("cp.async.commit_group;\n")
#define CP_WAIT3()  asm volatile("cp.async.wait_group 3;\n")

__device__ __forceinline__ void ldsm4(
    uint32_t& r0, uint32_t& r1, uint32_t& r2, uint32_t& r3, uint32_t addr)
{
    asm volatile(
        "ldmatrix.sync.aligned.m8n8.x4.shared.b16 {%0,%1,%2,%3}, [%4];"
        : "=r"(r0), "=r"(r1), "=r"(r2), "=r"(r3) : "r"(addr));
}

__global__ __launch_bounds__(512, 1) void gemm_f16(
    const __half* __restrict__ A, const __half* __restrict__ Bt,
    const float* __restrict__ bias, const float* __restrict__ res,
    void* __restrict__ Cout, int M, int N, int K, int mode)
{
    extern __shared__ char dynsmem[];
    int tid  = threadIdx.x;
    int bm   = blockIdx.y * BM;
    int bn   = blockIdx.x * BN;
    int warp = tid >> 5, lane = tid & 31;
    int g    = lane >> 2, tg = lane & 3;
    int warpM = (warp >> 2) * 64;   // 4 M-warps * 64 = 256
    int warpN = (warp & 3) * 32;    // 4 N-warps * 32 = 128

    // A fill: row = tid>>1 (0..255), two 16B chunks at (tid&1)*32 bytes
    int arow = tid >> 1, asel = tid & 1;
    // B fill: row = tid>>2 (0..127), one 16B chunk at (tid&3)*16 bytes
    int brow = tid >> 2, bsel = tid & 3;

    uint32_t sbase = (uint32_t)__cvta_generic_to_shared(dynsmem);
    const __half* Ag = A  + (size_t)(bm + arow) * K + asel * 16;
    const __half* Bg = Bt + (size_t)(bn + brow) * K + bsel * 8;

    auto PF = [&](int it) {
        int k0 = it * HBK;
        uint32_t base = sbase + (it % NSTG) * STG;
        uint32_t soff = arow * 80 + asel * 32;
        cp16(base + soff,      Ag + k0);
        cp16(base + soff + 16, Ag + k0 + 8);
        cp16(base + A_BYTES + brow * 80 + bsel * 16, Bg + k0);
        CP_COMMIT();
    };

    float acc[4][4][4];
    #pragma unroll
    for (int i = 0; i < 4; i++)
        #pragma unroll
        for (int j = 0; j < 4; j++)
            #pragma unroll
            for (int l = 0; l < 4; l++) acc[i][j][l] = 0.f;

    uint32_t a_lane = (uint32_t)((warpM + (lane & 15)) * 80 + (lane >> 4) * 16);
    uint32_t b_lane = (uint32_t)((warpN + (lane & 15)) * 80 + (lane >> 4) * 16);

    int nIter = K / HBK;
    PF(0); PF(1); PF(2); PF(3);

    for (int it = 0; it < nIter; ++it) {
        CP_WAIT3();
        __syncthreads();
        if (it + 4 < nIter) PF(it + 4);
        else                CP_COMMIT();

        uint32_t Abase = sbase + (it % NSTG) * STG + a_lane;
        uint32_t Bbase = sbase + (it % NSTG) * STG + A_BYTES + b_lane;

        #pragma unroll
        for (int ks = 0; ks < 2; ks++) {
            uint32_t af[4][4];
            #pragma unroll
            for (int mt = 0; mt < 4; mt++)
                ldsm4(af[mt][0], af[mt][1], af[mt][2], af[mt][3],
                      Abase + mt * (16 * 80) + ks * 32);

            uint32_t bq[2][4];
            #pragma unroll
            for (int n2 = 0; n2 < 2; n2++)
                ldsm4(bq[n2][0], bq[n2][1], bq[n2][2], bq[n2][3],
                      Bbase + n2 * (16 * 80) + ks * 32);

            #pragma unroll
            for (int mt = 0; mt < 4; mt++)
                #pragma unroll
                for (int nt = 0; nt < 4; nt++) {
                    uint32_t b0 = bq[nt >> 1][nt & 1];
                    uint32_t b1 = bq[nt >> 1][2 + (nt & 1)];
                    asm volatile(
                        "mma.sync.aligned.m16n8k16.row.col.f32.f16.f16.f32 "
                        "{%0,%1,%2,%3}, {%4,%5,%6,%7}, {%8,%9}, {%0,%1,%2,%3};"
                        : "+f"(acc[mt][nt][0]), "+f"(acc[mt][nt][1]),
                          "+f"(acc[mt][nt][2]), "+f"(acc[mt][nt][3])
                        : "r"(af[mt][0]), "r"(af[mt][1]),
                          "r"(af[mt][2]), "r"(af[mt][3]),
                          "r"(b0), "r"(b1));
                }
        }
    }

    #pragma unroll
    for (int mt = 0; mt < 4; mt++) {
        int r0 = bm + warpM + mt * 16 + g;
        #pragma unroll
        for (int nt = 0; nt < 4; nt++) {
            int col = bn + warpN + nt * 8 + tg * 2;
            #pragma unroll
            for (int half = 0; half < 2; half++) {
                int row = r0 + half * 8;
                float v0 = acc[mt][nt][half * 2 + 0] + bias[col];
                float v1 = acc[mt][nt][half * 2 + 1] + bias[col + 1];
                if (mode & 1) {
                    v0 = 0.5f * v0 * (1.0f + erff(v0 * 0.70710678118654752f));
                    v1 = 0.5f * v1 * (1.0f + erff(v1 * 0.70710678118654752f));
                }
                int orow = row;
                if (mode & 4) orow = win_row_to_token(row);
                if (mode & 2) {
                    __half2* cp =
                        (__half2*)((__half*)Cout + (size_t)orow * N + col);
                    *cp = __floats2half2_rn(v0, v1);
                } else {
                    if (res) {
                        v0 += res[(size_t)orow * N + col];
                        v1 += res[(size_t)orow * N + col + 1];
                    }
                    float2 o; o.x = v0; o.y = v1;
                    *(float2*)((float*)Cout + (size_t)orow * N + col) = o;
                }
            }
        }
    }
}

// ---------------- attention (fp16 qkv input): block per (window, head) ------
__global__ __launch_bounds__(64) void attn_kernel(
    const __half* __restrict__ qkv, const float* __restrict__ tau,
    const float* __restrict__ rpb, __half* __restrict__ ctx)
{
    __shared__ float sk[NTOK * HD];
    __shared__ float sv[NTOK * HD];
    __shared__ float sinvk[NTOK];
    __shared__ float srpb[225];

    int blk = blockIdx.x;
    int win = blk / NHEADS;
    int h   = blk - win * NHEADS;
    int t   = threadIdx.x;

    const size_t base = (size_t)win * NTOK * QKVN;
    int qoff = h * HD;

    // fill k/v smem: 256 chunks of 8 halves each
    for (int i = t; i < 256; i += 64) {
        int row = i >> 2;
        int d8  = (i & 3) * 8;
        size_t gg = base + (size_t)row * QKVN;
        uint4 ku = *(const uint4*)(qkv + gg + 384 + qoff + d8);
        uint4 vu = *(const uint4*)(qkv + gg + 768 + qoff + d8);
        const __half2* kh = (const __half2*)&ku;
        const __half2* vh = (const __half2*)&vu;
        #pragma unroll
        for (int j = 0; j < 4; j++) {
            float2 kf = __half22float2(kh[j]);
            float2 vf = __half22float2(vh[j]);
            sk[row * HD + d8 + 2 * j]     = kf.x;
            sk[row * HD + d8 + 2 * j + 1] = kf.y;
            sv[row * HD + d8 + 2 * j]     = vf.x;
            sv[row * HD + d8 + 2 * j + 1] = vf.y;
        }
    }
    for (int i = t; i < 225; i += 64) srpb[i] = rpb[i * NHEADS + h];
    __syncthreads();

    float qreg[HD];
    float qss = 0.f, kss = 0.f;
    const __half* qp = qkv + base + (size_t)t * QKVN + qoff;
    #pragma unroll
    for (int d8 = 0; d8 < HD; d8 += 8) {
        uint4 qu = *(const uint4*)(qp + d8);
        const __half2* qh = (const __half2*)&qu;
        #pragma unroll
        for (int j = 0; j < 4; j++) {
            float2 qf = __half22float2(qh[j]);
            qreg[d8 + 2 * j]     = qf.x;
            qreg[d8 + 2 * j + 1] = qf.y;
            qss += qf.x * qf.x + qf.y * qf.y;
        }
    }
    #pragma unroll
    for (int d = 0; d < HD; d++) {
        float kv = sk[t * HD + d];
        kss += kv * kv;
    }
    float invq = 1.0f / fmaxf(sqrtf(qss), 1e-12f);
    sinvk[t]   = 1.0f / fmaxf(sqrtf(kss), 1e-12f);
    __syncthreads();

    float sc = invq / fmaxf(tau[h], 1e-3f);

    int wimg = win & 63;
    int wh = wimg >> 3, ww = wimg & 7;
    int ni = t >> 3, nj = t & 7;
    int yn = wh * 8 + ni, xn = ww * 8 + nj;
    int regn = (yn < 56 ? 0 : (yn < 60 ? 1 : 2)) * 3 + (xn < 56 ? 0 : (xn < 60 ? 1 : 2));

    float sum = 0.f;
    float accv[HD] = {};
    #pragma unroll 8
    for (int m = 0; m < NTOK; m++) {
        float dot = 0.f;
        #pragma unroll
        for (int d4 = 0; d4 < HD; d4 += 4) {
            float4 kv = *(const float4*)&sk[m * HD + d4];
            dot += qreg[d4] * kv.x + qreg[d4 + 1] * kv.y
                 + qreg[d4 + 2] * kv.z + qreg[d4 + 3] * kv.w;
        }
        int mi = m >> 3, mj = m & 7;
        float val = dot * sc * sinvk[m] + srpb[(ni - mi + 7) * 15 + (nj - mj + 7)];
        int ym = wh * 8 + mi, xm = ww * 8 + mj;
        int regm = (ym < 56 ? 0 : (ym < 60 ? 1 : 2)) * 3
                 + (xm < 56 ? 0 : (xm < 60 ? 1 : 2));
        if (regm != regn) val -= 1e9f;
        float e = __expf(val);
        sum += e;
        #pragma unroll
        for (int d4 = 0; d4 < HD; d4 += 4) {
            float4 vv = *(const float4*)&sv[m * HD + d4];
            accv[d4]     += e * vv.x;
            accv[d4 + 1] += e * vv.y;
            accv[d4 + 2] += e * vv.z;
            accv[d4 + 3] += e * vv.w;
        }
    }

    float rinv = 1.0f / sum;
    __half2* op = (__half2*)(ctx + (size_t)(win * NTOK + t) * DIMC + qoff);
    #pragma unroll
    for (int d = 0; d < HD / 2; d++)
        op[d] = __floats2half2_rn(accv[2 * d] * rinv, accv[2 * d + 1] * rinv);
}

// ---------------- launcher --------------------------------------------------
extern "C" void kernel_launch(void* const* d_in, const int* in_sizes, int n_in,
                              void* d_out, int out_size)
{
    const float* x      = (const float*)d_in[0];
    const float* nag    = (const float*)d_in[3];
    const float* nab    = (const float*)d_in[4];
    const float* qkv_w  = (const float*)d_in[5];
    const float* qkv_b  = (const float*)d_in[6];
    const float* proj_w = (const float*)d_in[7];
    const float* proj_b = (const float*)d_in[8];
    const float* tau    = (const float*)d_in[9];
    const float* rpb    = (const float*)d_in[10];
    const float* nmg    = (const float*)d_in[11];
    const float* nmb    = (const float*)d_in[12];
    const float* fc1w   = (const float*)d_in[13];
    const float* fc1b   = (const float*)d_in[14];
    const float* fc2w   = (const float*)d_in[15];
    const float* fc2b   = (const float*)d_in[16];
    float* out = (float*)d_out;

    static float *pa=nullptr,*pb=nullptr,*pc=nullptr,*pd=nullptr;
    static __half *pw=nullptr;
    if (!pa) {
        cudaGetSymbolAddress((void**)&pa, g_a);
        cudaGetSymbolAddress((void**)&pb, g_b);
        cudaGetSymbolAddress((void**)&pc, g_c);
        cudaGetSymbolAddress((void**)&pd, g_d);
        cudaGetSymbolAddress((void**)&pw, g_w);
        cudaFuncSetAttribute(gemm_f16,
            cudaFuncAttributeMaxDynamicSharedMemorySize, NSTG * STG);
    }
    __half* wq  = pw;                 // [1152][384]
    __half* wp  = wq + 442368;        // [384][384]
    __half* w1t = wp + 147456;        // [1536][384]
    __half* w2t = w1t + 589824;       // [384][1536]

    const int gsmem = NSTG * STG;

    // launch order: 4th launch (ncu's pick) = qkv GEMM
    transpose_f16_kernel<<<dim3(QKVN/32, DIMC/32), 256>>>(qkv_w, wq, DIMC, QKVN);
    ln_kernel<<<NROWS, 128>>>(x, nag, nab, (__half*)pa, 1);
    transpose_f16_kernel<<<dim3(DIMC/32, DIMC/32), 256>>>(proj_w, wp, DIMC, DIMC);
    // 4) qkv GEMM -> g_b fp16
    gemm_f16<<<dim3(QKVN/BN, NROWS/BM), 512, gsmem>>>(
        (const __half*)pa, wq, qkv_b, nullptr, pb, NROWS, QKVN, DIMC, 2);
    // 5) attention -> g_c fp16
    attn_kernel<<<(NROWS/NTOK)*NHEADS, 64>>>((const __half*)pb, tau, rpb, (__half*)pc);
    // 6) proj GEMM + scatter + residual -> g_d fp32 (token order)
    gemm_f16<<<dim3(DIMC/BN, NROWS/BM), 512, gsmem>>>(
        (const __half*)pc, wp, proj_b, x, pd, NROWS, DIMC, DIMC, 4);
    // 7) LN2 -> g_a fp16
    ln_kernel<<<NROWS, 128>>>(pd, nmg, nmb, (__half*)pa, 0);
    transpose_f16_kernel<<<dim3(HIDF/32, DIMC/32), 256>>>(fc1w, w1t, DIMC, HIDF);
    transpose_f16_kernel<<<dim3(DIMC/32, HIDF/32), 256>>>(fc2w, w2t, HIDF, DIMC);
    // 10) fc1 + GELU -> g_b fp16
    gemm_f16<<<dim3(HIDF/BN, NROWS/BM), 512, gsmem>>>(
        (const __half*)pa, w1t, fc1b, nullptr, pb, NROWS, HIDF, DIMC, 1 | 2);
    // 11) fc2 + residual -> d_out fp32
    gemm_f16<<<dim3(DIMC/BN, NROWS/BM), 512, gsmem>>>(
        (const __half*)pb, w2t, fc2b, pd, out, NROWS, DIMC, HIDF, 0);
}

// round 12
// speedup vs baseline: 1.0525x; 1.0525x over previous
#include <cuda_runtime.h>
#include <cuda_fp16.h>
#include <math.h>
#include <stdint.h>
#include <stddef.h>

// ---------------- problem constants ----------------
#define DIMC   384
#define NHEADS 12
#define HD     32
#define NTOK   64
#define NROWS  65536
#define HIDF   1536
#define QKVN   1152

// ---------------- scratch ----------------
__device__ float g_a[(size_t)NROWS * DIMC];   // ln outs (fp16 payload)
__device__ float g_b[(size_t)NROWS * HIDF];   // qkv fp16 / gelu out fp16
__device__ float g_c[(size_t)NROWS * DIMC];   // attention ctx (fp16 payload)
__device__ float g_d[(size_t)NROWS * DIMC];   // x + attn (token order, fp32)
// fp16 transposed weights [N][K]
__device__ __half g_w[442368 + 147456 + 589824 + 589824];

__device__ __forceinline__ int win_row_to_token(int r) {
    int b   = r >> 12;
    int rem = r & 4095;
    int wh  = rem >> 9;
    int ww  = (rem >> 6) & 7;
    int n   = rem & 63;
    int ys  = (wh * 8 + (n >> 3) + 4) & 63;
    int xs  = (ww * 8 + (n & 7) + 4) & 63;
    return (b << 12) + ys * 64 + xs;
}

// ---------------- weight prep: W[K][N] fp32 -> Wt[N][K] fp16 ----------------
__global__ __launch_bounds__(256) void transpose_f16_kernel(
    const float* __restrict__ src, __half* __restrict__ dst, int K, int N)
{
    __shared__ float tile[32][33];
    int bx = blockIdx.x * 32;
    int by = blockIdx.y * 32;
    int tx = threadIdx.x & 31;
    int ty = threadIdx.x >> 5;
    #pragma unroll
    for (int j = 0; j < 32; j += 8)
        tile[ty + j][tx] = src[(size_t)(by + ty + j) * N + bx + tx];
    __syncthreads();
    #pragma unroll
    for (int j = 0; j < 32; j += 8)
        dst[(size_t)(bx + ty + j) * K + by + tx] = __float2half_rn(tile[tx][ty + j]);
}

// ---------------- LayerNorm: warp-per-row, 4 rows/block, fp16 out -----------
__global__ __launch_bounds__(128) void ln_kernel(
    const float* __restrict__ x, const float* __restrict__ gam,
    const float* __restrict__ bet, __half* __restrict__ out, int gather)
{
    int warp = threadIdx.x >> 5, lane = threadIdx.x & 31;
    int r    = blockIdx.x * 4 + warp;
    int src  = gather ? win_row_to_token(r) : r;
    const float4* xp = (const float4*)(x + (size_t)src * DIMC);

    float4 v[3];
    float s = 0.f, ss = 0.f;
    #pragma unroll
    for (int j = 0; j < 3; j++) {
        v[j] = xp[lane + 32 * j];
        s  += v[j].x + v[j].y + v[j].z + v[j].w;
        ss += v[j].x * v[j].x + v[j].y * v[j].y + v[j].z * v[j].z + v[j].w * v[j].w;
    }
    #pragma unroll
    for (int o = 16; o; o >>= 1) {
        s  += __shfl_xor_sync(0xffffffffu, s,  o);
        ss += __shfl_xor_sync(0xffffffffu, ss, o);
    }
    float mu  = s * (1.0f / DIMC);
    float var = ss * (1.0f / DIMC) - mu * mu;
    float inv = rsqrtf(var + 1e-5f);

    __half2* op = (__half2*)(out + (size_t)r * DIMC);
    const float4* gp = (const float4*)gam;
    const float4* bp = (const float4*)bet;
    #pragma unroll
    for (int j = 0; j < 3; j++) {
        float4 gv = gp[lane + 32 * j];
        float4 bv = bp[lane + 32 * j];
        float o0 = (v[j].x - mu) * inv * gv.x + bv.x;
        float o1 = (v[j].y - mu) * inv * gv.y + bv.y;
        float o2 = (v[j].z - mu) * inv * gv.z + bv.z;
        float o3 = (v[j].w - mu) * inv * gv.w + bv.w;
        op[lane * 2 + 64 * j]     = __floats2half2_rn(o0, o1);
        op[lane * 2 + 64 * j + 1] = __floats2half2_rn(o2, o3);
    }
}

// ================= fp16 mma.sync GEMM, 128x64 tile, 24 warps/SM ==============
// A[M][K] fp16 row-major, Bt[N][K] fp16, both k-contiguous.
// 4-stage cp.async ring, one __syncthreads per iteration, LDSM fragments.
// Warp tile 32x32 (acc 32 regs) -> ~75 regs/thread -> 3 CTAs/SM (24 warps).
// mode bits: 1 = exact GELU, 2 = fp16 output, 4 = scatter rows + residual
#define BM 128
#define BN 64
#define HBK 32
#define A_BYTES (BM * 80)              // 10240
#define B_BYTES (BN * 80)              // 5120
#define STG     (A_BYTES + B_BYTES)    // 15360
#define NSTG    4

__device__ __forceinline__ void cp16(uint32_t smem, const void* g) {
    asm volatile("cp.async.cg.shared.global [%0], [%1], 16;\n"
                 :: "r"(smem), "l"(g));
}
#define CP_COMMIT() asm volatile("cp.async.commit_group;\n")
#define CP_WAIT2()  asm volatile("cp.async.wait_group 2;\n")

__device__ __forceinline__ void ldsm4(
    uint32_t& r0, uint32_t& r1, uint32_t& r2, uint32_t& r3, uint32_t addr)
{
    asm volatile(
        "ldmatrix.sync.aligned.m8n8.x4.shared.b16 {%0,%1,%2,%3}, [%4];"
        : "=r"(r0), "=r"(r1), "=r"(r2), "=r"(r3) : "r"(addr));
}

__global__ __launch_bounds__(256, 3) void gemm_f16(
    const __half* __restrict__ A, const __half* __restrict__ Bt,
    const float* __restrict__ bias, const float* __restrict__ res,
    void* __restrict__ Cout, int M, int N, int K, int mode)
{
    extern __shared__ char dynsmem[];
    int tid  = threadIdx.x;
    int bm   = blockIdx.y * BM;
    int bn   = blockIdx.x * BN;
    int warp = tid >> 5, lane = tid & 31;
    int g    = lane >> 2, tg = lane & 3;
    int warpM = (warp >> 1) * 32;   // 4 M-warps * 32 = 128
    int warpN = (warp & 1) * 32;    // 2 N-warps * 32 = 64

    // A fill: row = tid>>1 (0..127), two 16B chunks at (tid&1)*32 bytes
    int arow = tid >> 1, asel = tid & 1;
    // B fill: row = tid>>2 (0..63), one 16B chunk at (tid&3)*16 bytes
    int brow = tid >> 2, bsel = tid & 3;

    uint32_t sbase = (uint32_t)__cvta_generic_to_shared(dynsmem);
    const __half* Ag = A  + (size_t)(bm + arow) * K + asel * 16;
    const __half* Bg = Bt + (size_t)(bn + brow) * K + bsel * 8;

    auto PF = [&](int it) {
        int k0 = it * HBK;
        uint32_t base = sbase + (it & 3) * STG;
        uint32_t soff = arow * 80 + asel * 32;
        cp16(base + soff,      Ag + k0);
        cp16(base + soff + 16, Ag + k0 + 8);
        cp16(base + A_BYTES + brow * 80 + bsel * 16, Bg + k0);
        CP_COMMIT();
    };

    float acc[2][4][4];
    #pragma unroll
    for (int i = 0; i < 2; i++)
        #pragma unroll
        for (int j = 0; j < 4; j++)
            #pragma unroll
            for (int l = 0; l < 4; l++) acc[i][j][l] = 0.f;

    uint32_t a_lane = (uint32_t)((warpM + (lane & 15)) * 80 + (lane >> 4) * 16);
    uint32_t b_lane = (uint32_t)((warpN + (lane & 15)) * 80 + (lane >> 4) * 16);

    int nIter = K / HBK;
    PF(0); PF(1); PF(2);

    for (int it = 0; it < nIter; ++it) {
        CP_WAIT2();
        __syncthreads();
        if (it + 3 < nIter) PF(it + 3);
        else                CP_COMMIT();

        uint32_t Abase = sbase + (it & 3) * STG + a_lane;
        uint32_t Bbase = sbase + (it & 3) * STG + A_BYTES + b_lane;

        #pragma unroll
        for (int ks = 0; ks < 2; ks++) {
            uint32_t af[2][4];
            #pragma unroll
            for (int mt = 0; mt < 2; mt++)
                ldsm4(af[mt][0], af[mt][1], af[mt][2], af[mt][3],
                      Abase + mt * (16 * 80) + ks * 32);

            uint32_t bq[2][4];
            #pragma unroll
            for (int n2 = 0; n2 < 2; n2++)
                ldsm4(bq[n2][0], bq[n2][1], bq[n2][2], bq[n2][3],
                      Bbase + n2 * (16 * 80) + ks * 32);

            #pragma unroll
            for (int mt = 0; mt < 2; mt++)
                #pragma unroll
                for (int nt = 0; nt < 4; nt++) {
                    uint32_t b0 = bq[nt >> 1][nt & 1];
                    uint32_t b1 = bq[nt >> 1][2 + (nt & 1)];
                    asm volatile(
                        "mma.sync.aligned.m16n8k16.row.col.f32.f16.f16.f32 "
                        "{%0,%1,%2,%3}, {%4,%5,%6,%7}, {%8,%9}, {%0,%1,%2,%3};"
                        : "+f"(acc[mt][nt][0]), "+f"(acc[mt][nt][1]),
                          "+f"(acc[mt][nt][2]), "+f"(acc[mt][nt][3])
                        : "r"(af[mt][0]), "r"(af[mt][1]),
                          "r"(af[mt][2]), "r"(af[mt][3]),
                          "r"(b0), "r"(b1));
                }
        }
    }

    #pragma unroll
    for (int mt = 0; mt < 2; mt++) {
        int r0 = bm + warpM + mt * 16 + g;
        #pragma unroll
        for (int nt = 0; nt < 4; nt++) {
            int col = bn + warpN + nt * 8 + tg * 2;
            #pragma unroll
            for (int half = 0; half < 2; half++) {
                int row = r0 + half * 8;
                float v0 = acc[mt][nt][half * 2 + 0] + bias[col];
                float v1 = acc[mt][nt][half * 2 + 1] + bias[col + 1];
                if (mode & 1) {
                    v0 = 0.5f * v0 * (1.0f + erff(v0 * 0.70710678118654752f));
                    v1 = 0.5f * v1 * (1.0f + erff(v1 * 0.70710678118654752f));
                }
                int orow = row;
                if (mode & 4) orow = win_row_to_token(row);
                if (mode & 2) {
                    __half2* cp =
                        (__half2*)((__half*)Cout + (size_t)orow * N + col);
                    *cp = __floats2half2_rn(v0, v1);
                } else {
                    if (res) {
                        v0 += res[(size_t)orow * N + col];
                        v1 += res[(size_t)orow * N + col + 1];
                    }
                    float2 o; o.x = v0; o.y = v1;
                    *(float2*)((float*)Cout + (size_t)orow * N + col) = o;
                }
            }
        }
    }
}

// ---------------- attention (fp16 qkv input): block per (window, head) ------
__global__ __launch_bounds__(64) void attn_kernel(
    const __half* __restrict__ qkv, const float* __restrict__ tau,
    const float* __restrict__ rpb, __half* __restrict__ ctx)
{
    __shared__ float sk[NTOK * HD];
    __shared__ float sv[NTOK * HD];
    __shared__ float sinvk[NTOK];
    __shared__ float srpb[225];

    int blk = blockIdx.x;
    int win = blk / NHEADS;
    int h   = blk - win * NHEADS;
    int t   = threadIdx.x;

    const size_t base = (size_t)win * NTOK * QKVN;
    int qoff = h * HD;

    for (int i = t; i < 256; i += 64) {
        int row = i >> 2;
        int d8  = (i & 3) * 8;
        size_t gg = base + (size_t)row * QKVN;
        uint4 ku = *(const uint4*)(qkv + gg + 384 + qoff + d8);
        uint4 vu = *(const uint4*)(qkv + gg + 768 + qoff + d8);
        const __half2* kh = (const __half2*)&ku;
        const __half2* vh = (const __half2*)&vu;
        #pragma unroll
        for (int j = 0; j < 4; j++) {
            float2 kf = __half22float2(kh[j]);
            float2 vf = __half22float2(vh[j]);
            sk[row * HD + d8 + 2 * j]     = kf.x;
            sk[row * HD + d8 + 2 * j + 1] = kf.y;
            sv[row * HD + d8 + 2 * j]     = vf.x;
            sv[row * HD + d8 + 2 * j + 1] = vf.y;
        }
    }
    for (int i = t; i < 225; i += 64) srpb[i] = rpb[i * NHEADS + h];
    __syncthreads();

    float qreg[HD];
    float qss = 0.f, kss = 0.f;
    const __half* qp = qkv + base + (size_t)t * QKVN + qoff;
    #pragma unroll
    for (int d8 = 0; d8 < HD; d8 += 8) {
        uint4 qu = *(const uint4*)(qp + d8);
        const __half2* qh = (const __half2*)&qu;
        #pragma unroll
        for (int j = 0; j < 4; j++) {
            float2 qf = __half22float2(qh[j]);
            qreg[d8 + 2 * j]     = qf.x;
            qreg[d8 + 2 * j + 1] = qf.y;
            qss += qf.x * qf.x + qf.y * qf.y;
        }
    }
    #pragma unroll
    for (int d = 0; d < HD; d++) {
        float kv = sk[t * HD + d];
        kss += kv * kv;
    }
    float invq = 1.0f / fmaxf(sqrtf(qss), 1e-12f);
    sinvk[t]   = 1.0f / fmaxf(sqrtf(kss), 1e-12f);
    __syncthreads();

    float sc = invq / fmaxf(tau[h], 1e-3f);

    int wimg = win & 63;
    int wh = wimg >> 3, ww = wimg & 7;
    int ni = t >> 3, nj = t & 7;
    int yn = wh * 8 + ni, xn = ww * 8 + nj;
    int regn = (yn < 56 ? 0 : (yn < 60 ? 1 : 2)) * 3 + (xn < 56 ? 0 : (xn < 60 ? 1 : 2));

    float sum = 0.f;
    float accv[HD] = {};
    #pragma unroll 8
    for (int m = 0; m < NTOK; m++) {
        float dot = 0.f;
        #pragma unroll
        for (int d4 = 0; d4 < HD; d4 += 4) {
            float4 kv = *(const float4*)&sk[m * HD + d4];
            dot += qreg[d4] * kv.x + qreg[d4 + 1] * kv.y
                 + qreg[d4 + 2] * kv.z + qreg[d4 + 3] * kv.w;
        }
        int mi = m >> 3, mj = m & 7;
        float val = dot * sc * sinvk[m] + srpb[(ni - mi + 7) * 15 + (nj - mj + 7)];
        int ym = wh * 8 + mi, xm = ww * 8 + mj;
        int regm = (ym < 56 ? 0 : (ym < 60 ? 1 : 2)) * 3
                 + (xm < 56 ? 0 : (xm < 60 ? 1 : 2));
        if (regm != regn) val -= 1e9f;
        float e = __expf(val);
        sum += e;
        #pragma unroll
        for (int d4 = 0; d4 < HD; d4 += 4) {
            float4 vv = *(const float4*)&sv[m * HD + d4];
            accv[d4]     += e * vv.x;
            accv[d4 + 1] += e * vv.y;
            accv[d4 + 2] += e * vv.z;
            accv[d4 + 3] += e * vv.w;
        }
    }

    float rinv = 1.0f / sum;
    __half2* op = (__half2*)(ctx + (size_t)(win * NTOK + t) * DIMC + qoff);
    #pragma unroll
    for (int d = 0; d < HD / 2; d++)
        op[d] = __floats2half2_rn(accv[2 * d] * rinv, accv[2 * d + 1] * rinv);
}

// ---------------- launcher --------------------------------------------------
extern "C" void kernel_launch(void* const* d_in, const int* in_sizes, int n_in,
                              void* d_out, int out_size)
{
    const float* x      = (const float*)d_in[0];
    const float* nag    = (const float*)d_in[3];
    const float* nab    = (const float*)d_in[4];
    const float* qkv_w  = (const float*)d_in[5];
    const float* qkv_b  = (const float*)d_in[6];
    const float* proj_w = (const float*)d_in[7];
    const float* proj_b = (const float*)d_in[8];
    const float* tau    = (const float*)d_in[9];
    const float* rpb    = (const float*)d_in[10];
    const float* nmg    = (const float*)d_in[11];
    const float* nmb    = (const float*)d_in[12];
    const float* fc1w   = (const float*)d_in[13];
    const float* fc1b   = (const float*)d_in[14];
    const float* fc2w   = (const float*)d_in[15];
    const float* fc2b   = (const float*)d_in[16];
    float* out = (float*)d_out;

    static float *pa=nullptr,*pb=nullptr,*pc=nullptr,*pd=nullptr;
    static __half *pw=nullptr;
    if (!pa) {
        cudaGetSymbolAddress((void**)&pa, g_a);
        cudaGetSymbolAddress((void**)&pb, g_b);
        cudaGetSymbolAddress((void**)&pc, g_c);
        cudaGetSymbolAddress((void**)&pd, g_d);
        cudaGetSymbolAddress((void**)&pw, g_w);
        cudaFuncSetAttribute(gemm_f16,
            cudaFuncAttributeMaxDynamicSharedMemorySize, NSTG * STG);
    }
    __half* wq  = pw;                 // [1152][384]
    __half* wp  = wq + 442368;        // [384][384]
    __half* w1t = wp + 147456;        // [1536][384]
    __half* w2t = w1t + 589824;       // [384][1536]

    const int gsmem = NSTG * STG;

    // launch order: 4th launch (ncu's pick) = qkv GEMM
    transpose_f16_kernel<<<dim3(QKVN/32, DIMC/32), 256>>>(qkv_w, wq, DIMC, QKVN);
    ln_kernel<<<NROWS/4, 128>>>(x, nag, nab, (__half*)pa, 1);
    transpose_f16_kernel<<<dim3(DIMC/32, DIMC/32), 256>>>(proj_w, wp, DIMC, DIMC);
    // 4) qkv GEMM -> g_b fp16
    gemm_f16<<<dim3(QKVN/BN, NROWS/BM), 256, gsmem>>>(
        (const __half*)pa, wq, qkv_b, nullptr, pb, NROWS, QKVN, DIMC, 2);
    // 5) attention -> g_c fp16
    attn_kernel<<<(NROWS/NTOK)*NHEADS, 64>>>((const __half*)pb, tau, rpb, (__half*)pc);
    // 6) proj GEMM + scatter + residual -> g_d fp32 (token order)
    gemm_f16<<<dim3(DIMC/BN, NROWS/BM), 256, gsmem>>>(
        (const __half*)pc, wp, proj_b, x, pd, NROWS, DIMC, DIMC, 4);
    // 7) LN2 -> g_a fp16
    ln_kernel<<<NROWS/4, 128>>>(pd, nmg, nmb, (__half*)pa, 0);
    transpose_f16_kernel<<<dim3(HIDF/32, DIMC/32), 256>>>(fc1w, w1t, DIMC, HIDF);
    transpose_f16_kernel<<<dim3(DIMC/32, HIDF/32), 256>>>(fc2w, w2t, HIDF, DIMC);
    // 10) fc1 + GELU -> g_b fp16
    gemm_f16<<<dim3(HIDF/BN, NROWS/BM), 256, gsmem>>>(
        (const __half*)pa, w1t, fc1b, nullptr, pb, NROWS, HIDF, DIMC, 1 | 2);
    // 11) fc2 + residual -> d_out fp32
    gemm_f16<<<dim3(DIMC/BN, NROWS/BM), 256, gsmem>>>(
        (const __half*)pb, w2t, fc2b, pd, out, NROWS, DIMC, HIDF, 0);
}